// round 12
// baseline (speedup 1.0000x reference)
#include <cuda_runtime.h>
#include <cuda_bf16.h>
#include <cstdint>

#define NN 8192
#define FF 64
#define BB 4
#define NCOL 256
#define KHALF 4096
#define KT 32
#define NITER (KHALF / KT)   // 128
#define MT 128
#define RST 80               // smem row stride bytes

__device__ unsigned short g_Z0[(size_t)NCOL * NN];   // [n=b*64+f][k] bf16 hi
__device__ unsigned short g_Z1s[(size_t)NCOL * NN];  // lo
__device__ float g_P[2][(size_t)NN * NCOL];

// gemm smem per buffer: Ahi(10240) Alo(10240) Bhi(10240) Blo(10240) = 40960; x2
#define BUFB 40960
#define GEMM_SMEM (2 * BUFB)

__device__ __forceinline__ void cp16(uint32_t dst, const void* gsrc) {
    asm volatile("cp.async.cg.shared.global [%0], [%1], 16;\n" :: "r"(dst), "l"(gsrc));
}
__device__ __forceinline__ void ldm4(uint32_t& r0, uint32_t& r1, uint32_t& r2,
                                     uint32_t& r3, uint32_t a) {
    asm volatile("ldmatrix.sync.aligned.m8n8.x4.shared.b16 {%0,%1,%2,%3}, [%4];"
                 : "=r"(r0), "=r"(r1), "=r"(r2), "=r"(r3) : "r"(a));
}
__device__ __forceinline__ void mma_bf16(float* d, const uint32_t* a, const uint32_t* b) {
    asm volatile(
        "mma.sync.aligned.m16n8k16.row.col.f32.bf16.bf16.f32 "
        "{%0,%1,%2,%3},{%4,%5,%6,%7},{%8,%9},{%0,%1,%2,%3};"
        : "+f"(d[0]), "+f"(d[1]), "+f"(d[2]), "+f"(d[3])
        : "r"(a[0]), "r"(a[1]), "r"(a[2]), "r"(a[3]), "r"(b[0]), "r"(b[1]));
}
__device__ __forceinline__ uint32_t cvt2(float hi, float lo) {
    uint32_t r;
    asm("cvt.rn.bf16x2.f32 %0, %1, %2;" : "=r"(r) : "f"(hi), "f"(lo));
    return r;
}
__device__ __forceinline__ void bsplit(float x, unsigned short& hi, unsigned short& lo) {
    __nv_bfloat16 h = __float2bfloat16_rn(x);
    float r = x - __bfloat162float(h);
    __nv_bfloat16 l = __float2bfloat16_rn(r);
    hi = *(unsigned short*)&h;
    lo = *(unsigned short*)&l;
}

// ---- split + transpose x: [b][k][f] fp32 -> [b*64+f][k] bf16 hi/lo (layer 0) ----
__global__ __launch_bounds__(256) void split_z_kernel(const float* __restrict__ Zin)
{
    __shared__ float s[64 * 65];
    const int b = blockIdx.y;
    const int k0 = blockIdx.x * 64;
    const int tid = threadIdx.x;
    #pragma unroll
    for (int i = 0; i < 16; i++) {
        int idx = tid + i * 256;
        int kr = idx >> 6, f = idx & 63;
        s[kr * 65 + f] = Zin[((size_t)b * NN + k0 + kr) * FF + f];
    }
    __syncthreads();
    #pragma unroll
    for (int i = 0; i < 16; i++) {
        int idx = tid + i * 256;
        int f = idx >> 6, kl = idx & 63;
        unsigned short h, l;
        bsplit(s[kl * 65 + f], h, l);
        size_t o = (size_t)(b * FF + f) * NN + k0 + kl;
        g_Z0[o] = h;
        g_Z1s[o] = l;
    }
}

// ---- GEMM: P[kh] = A[m-tile, khalf] @ Zfused (3-product bf16 split) ----
// 256 threads, 8 warps as 2M x 4N (warp tile 64x32), 2 CTAs/SM, in-reg A split.
__global__ __launch_bounds__(256, 2) void gemm_kernel(
    const float* __restrict__ A, float* __restrict__ P)
{
    extern __shared__ char smem[];
    const uint32_t sb = (uint32_t)__cvta_generic_to_shared(smem);
    const int tid = threadIdx.x;
    const int lane = tid & 31;
    const int warp = tid >> 5;
    const int g = lane >> 2;
    const int t = lane & 3;
    const int wm = (warp & 1) * 64;
    const int wn = (warp >> 1) * 32;

    const int m0 = blockIdx.x * MT;
    const int n0 = blockIdx.y * 128;
    const int kh = blockIdx.z;
    const size_t kbase = (size_t)kh * KHALF;

    // A loader: 4 float4 sites/thread. site = tid + i*256 -> row = tid>>3 + 32*i
    const int ar = tid >> 3;
    const int ac8 = tid & 7;
    const float* Ab = A + (size_t)(m0 + ar) * NN + kbase + ac8 * 4;
    const uint32_t asts = ar * RST + ac8 * 8;

    const uint32_t aoff = (uint32_t)(wm + (lane & 15)) * RST + ((lane & 16) ? 16 : 0);
    const uint32_t boff = (uint32_t)(wn + (lane & 7) + ((lane & 16) ? 8 : 0)) * RST +
                          ((lane & 8) ? 16 : 0);

    float acc[4][4][4] = {};
    float4 av[4];

    auto ldgA = [&](int kt) {
        const float* p = Ab + (size_t)kt * KT;
        #pragma unroll
        for (int i = 0; i < 4; i++)
            av[i] = __ldg((const float4*)(p + (size_t)(32 * i) * NN));
    };
    auto stsA = [&](int buf) {
        const uint32_t d0 = sb + buf * BUFB + asts;
        #pragma unroll
        for (int i = 0; i < 4; i++) {
            float4 v = av[i];
            uint32_t h01 = cvt2(v.y, v.x);
            uint32_t h23 = cvt2(v.w, v.z);
            float r0 = v.x - __uint_as_float(h01 << 16);
            float r1 = v.y - __uint_as_float(h01 & 0xFFFF0000u);
            float r2 = v.z - __uint_as_float(h23 << 16);
            float r3 = v.w - __uint_as_float(h23 & 0xFFFF0000u);
            uint32_t l01 = cvt2(r1, r0);
            uint32_t l23 = cvt2(r3, r2);
            uint32_t off = d0 + i * 32 * RST;
            asm volatile("st.shared.v2.b32 [%0], {%1,%2};" :: "r"(off), "r"(h01), "r"(h23));
            asm volatile("st.shared.v2.b32 [%0+10240], {%1,%2};" :: "r"(off), "r"(l01), "r"(l23));
        }
    };
    auto loadB = [&](int buf, int kt) {
        const size_t k0 = kbase + (size_t)kt * KT;
        const uint32_t d0 = sb + buf * BUFB + 20480;
        #pragma unroll
        for (int s = 0; s < 2; s++) {
            const unsigned short* src = s ? g_Z1s : g_Z0;
            #pragma unroll
            for (int i = 0; i < 2; i++) {
                int idx = tid + i * 256;
                int r = idx >> 2, c = idx & 3;
                cp16(d0 + s * 10240 + r * RST + c * 16,
                     src + (size_t)(n0 + r) * NN + k0 + c * 8);
            }
        }
    };

    ldgA(0);
    loadB(0, 0);
    asm volatile("cp.async.commit_group;\n" ::);

    for (int kt = 0; kt < NITER; kt++) {
        const int buf = kt & 1;
        stsA(buf);                          // split regs (tile kt) -> smem
        if (kt + 1 < NITER) {
            ldgA(kt + 1);                   // lands during mma below
            loadB(buf ^ 1, kt + 1);
            asm volatile("cp.async.commit_group;\n" ::);
            asm volatile("cp.async.wait_group 1;\n" ::);
        } else {
            asm volatile("cp.async.wait_group 0;\n" ::);
        }
        __syncthreads();

        const uint32_t abase = sb + buf * BUFB;
        #pragma unroll
        for (int kk = 0; kk < 2; kk++) {
            const uint32_t kbyte = kk * 32;
            const uint32_t aHi = abase + aoff + kbyte;
            const uint32_t aLo = aHi + 10240;
            const uint32_t bHi = abase + 20480 + boff + kbyte;
            const uint32_t bLo = bHi + 10240;

            uint32_t ah[4][4], bh[4][2];
            #pragma unroll
            for (int mi = 0; mi < 4; mi++)
                ldm4(ah[mi][0], ah[mi][1], ah[mi][2], ah[mi][3], aHi + mi * 16 * RST);
            #pragma unroll
            for (int p = 0; p < 2; p++)
                ldm4(bh[2 * p][0], bh[2 * p][1], bh[2 * p + 1][0], bh[2 * p + 1][1],
                     bHi + p * 16 * RST);
            #pragma unroll
            for (int mi = 0; mi < 4; mi++)
                #pragma unroll
                for (int ni = 0; ni < 4; ni++)
                    mma_bf16(acc[mi][ni], ah[mi], bh[ni]);   // hi*hi
            {
                uint32_t bl[4][2];
                #pragma unroll
                for (int p = 0; p < 2; p++)
                    ldm4(bl[2 * p][0], bl[2 * p][1], bl[2 * p + 1][0], bl[2 * p + 1][1],
                         bLo + p * 16 * RST);
                #pragma unroll
                for (int mi = 0; mi < 4; mi++)
                    #pragma unroll
                    for (int ni = 0; ni < 4; ni++)
                        mma_bf16(acc[mi][ni], ah[mi], bl[ni]);   // hi*lo
            }
            {
                uint32_t al[4][4];
                #pragma unroll
                for (int mi = 0; mi < 4; mi++)
                    ldm4(al[mi][0], al[mi][1], al[mi][2], al[mi][3], aLo + mi * 16 * RST);
                #pragma unroll
                for (int mi = 0; mi < 4; mi++)
                    #pragma unroll
                    for (int ni = 0; ni < 4; ni++)
                        mma_bf16(acc[mi][ni], al[mi], bh[ni]);   // lo*hi
            }
        }
        __syncthreads();
    }

    float* Pl = P + (size_t)kh * NN * NCOL;
    #pragma unroll
    for (int mi = 0; mi < 4; mi++) {
        const size_t r = (size_t)(m0 + wm + mi * 16 + g);
        #pragma unroll
        for (int ni = 0; ni < 4; ni++) {
            const int c = n0 + wn + ni * 8 + 2 * t;
            *(float2*)&Pl[r * NCOL + c] = make_float2(acc[mi][ni][0], acc[mi][ni][1]);
            *(float2*)&Pl[(r + 8) * NCOL + c] = make_float2(acc[mi][ni][2], acc[mi][ni][3]);
        }
    }
}

// ---- reduce: per-(64 rows x 1 batch) block. acc = relu((P0+P1) @ W) ----
#define HS_BYTES 18432
#define RED_SMEM (HS_BYTES + 16384)     // + W smem copy
__device__ __forceinline__ void reduce_compute2(
    float* Hs, float* Ws, const float* __restrict__ W, int m0, int b, int tid,
    float acc[16], int& row_o, int& fh_o)
{
    const float* P0 = g_P[0];
    const float* P1 = g_P[1];
    #pragma unroll
    for (int i = tid; i < 64 * 16; i += 256) {
        int r = i >> 4, q = i & 15;
        size_t gg = (size_t)(m0 + r) * NCOL + b * 64 + q * 4;
        float4 a = *(const float4*)&P0[gg];
        float4 b4 = *(const float4*)&P1[gg];
        *(float4*)&Hs[r * 68 + q * 4] =
            make_float4(a.x + b4.x, a.y + b4.y, a.z + b4.z, a.w + b4.w);
    }
    #pragma unroll
    for (int i = tid; i < 1024; i += 256)
        ((float4*)Ws)[i] = __ldg(((const float4*)W) + i);
    __syncthreads();

    const int row = tid >> 2;
    const int fh = tid & 3;
    row_o = row; fh_o = fh;
    const float* hb = &Hs[row * 68];
    const float4* wbase = (const float4*)(Ws + fh * 16);

    #pragma unroll 8
    for (int fp = 0; fp < 64; fp++) {
        float h = hb[fp];
        const float4* wr = wbase + fp * 16;
        float4 w0 = wr[0], w1 = wr[1], w2 = wr[2], w3 = wr[3];
        acc[0] += h * w0.x;  acc[1] += h * w0.y;  acc[2] += h * w0.z;  acc[3] += h * w0.w;
        acc[4] += h * w1.x;  acc[5] += h * w1.y;  acc[6] += h * w1.z;  acc[7] += h * w1.w;
        acc[8] += h * w2.x;  acc[9] += h * w2.y;  acc[10] += h * w2.z; acc[11] += h * w2.w;
        acc[12] += h * w3.x; acc[13] += h * w3.y; acc[14] += h * w3.z; acc[15] += h * w3.w;
    }
    #pragma unroll
    for (int j = 0; j < 16; j++) acc[j] = fmaxf(acc[j], 0.f);
}

__global__ __launch_bounds__(256) void reduce_w_kernel(
    const float* __restrict__ W, float* __restrict__ Zout)
{
    extern __shared__ char smemc[];
    float* Hs = (float*)smemc;
    float* Ws = (float*)(smemc + HS_BYTES);
    const int tid = threadIdx.x;
    const int m0 = blockIdx.x * 64;
    const int b = blockIdx.y;
    float acc[16] = {};
    int row, fh;
    reduce_compute2(Hs, Ws, W, m0, b, tid, acc, row, fh);

    float* op = Zout + ((size_t)b * NN + m0 + row) * FF + fh * 16;
    #pragma unroll
    for (int j = 0; j < 16; j += 4)
        *(float4*)&op[j] = make_float4(acc[j], acc[j + 1], acc[j + 2], acc[j + 3]);
}

// mid layer: write bf16 hi/lo splits transposed [n][k] -> g_Z0/g_Z1s
__global__ __launch_bounds__(256) void reduce_w_split_kernel(const float* __restrict__ W)
{
    extern __shared__ char smemc[];
    float* Hs = (float*)smemc;
    float* Ws = (float*)(smemc + HS_BYTES);
    const int tid = threadIdx.x;
    const int m0 = blockIdx.x * 64;
    const int b = blockIdx.y;
    float acc[16] = {};
    int row, fh;
    reduce_compute2(Hs, Ws, W, m0, b, tid, acc, row, fh);
    __syncthreads();     // Hs dead; reuse as transpose buffers

    unsigned short* Th = (unsigned short*)smemc;   // [64][72]
    unsigned short* Tl = Th + 64 * 72;
    #pragma unroll
    for (int j = 0; j < 16; j++) {
        int n = fh * 16 + j;
        unsigned short h, l;
        bsplit(acc[j], h, l);
        Th[n * 72 + row] = h;
        Tl[n * 72 + row] = l;
    }
    __syncthreads();

    const int nq = tid >> 2;      // local n 0..63
    const int q = tid & 3;        // 16-short chunk 0..3
    const uint4* sh = (const uint4*)&Th[nq * 72 + q * 16];
    const uint4* sl = (const uint4*)&Tl[nq * 72 + q * 16];
    uint4* dh = (uint4*)&g_Z0[(size_t)(b * 64 + nq) * NN + m0 + q * 16];
    uint4* dl = (uint4*)&g_Z1s[(size_t)(b * 64 + nq) * NN + m0 + q * 16];
    dh[0] = sh[0]; dh[1] = sh[1];
    dl[0] = sl[0]; dl[1] = sl[1];
}

extern "C" void kernel_launch(void* const* d_in, const int* in_sizes, int n_in,
                              void* d_out, int out_size)
{
    const float* x   = (const float*)d_in[0];
    const float* net = (const float*)d_in[2];
    const float* A   = (const float*)d_in[3];
    float* out       = (float*)d_out;

    float* P = nullptr;
    cudaGetSymbolAddress((void**)&P, g_P);

    cudaFuncSetAttribute(gemm_kernel,
                         cudaFuncAttributeMaxDynamicSharedMemorySize, GEMM_SMEM);
    cudaFuncSetAttribute(reduce_w_kernel,
                         cudaFuncAttributeMaxDynamicSharedMemorySize, RED_SMEM);
    cudaFuncSetAttribute(reduce_w_split_kernel,
                         cudaFuncAttributeMaxDynamicSharedMemorySize, RED_SMEM);

    dim3 ggrid(NN / MT, 2, 2);
    dim3 zgrid(NN / 64, BB);
    dim3 rgrid(NN / 64, BB);

    // layer 0
    split_z_kernel<<<zgrid, 256>>>(x);
    gemm_kernel<<<ggrid, 256, GEMM_SMEM>>>(A, P);
    reduce_w_split_kernel<<<rgrid, 256, RED_SMEM>>>(net);     // -> g_Z0/g_Z1s
    // layer 1
    gemm_kernel<<<ggrid, 256, GEMM_SMEM>>>(A, P);
    reduce_w_kernel<<<rgrid, 256, RED_SMEM>>>(net + FF * FF, out);
}